// round 3
// baseline (speedup 1.0000x reference)
#include <cuda_runtime.h>
#include <math.h>

// Problem constants: B=16, M=N=256, C=OUT=64, modes=32/axis, FF_HID=256.
// Slabs: 4096 = B*M (y-path) or B*N (x-path). Each slab: 256 positions x 64 ch.

#define PI_D 3.14159265358979323846

// ----------------------------- device scratch ------------------------------
__device__ float g_Ft [256 * 64];              // forward DFT, [n][kr] (kr = re/im interleaved)
__device__ float g_Cit[256 * 64];              // inverse DFT, [n][kr]
__device__ float g_w1t[2 * 32 * 64 * 64];      // [re|im][k][c][o]
__device__ float g_w2t[2 * 32 * 64 * 64];
__device__ float g_S[(size_t)4096 * 4096];     // spectra   [slab][kr][c]   (64 MB)
__device__ float g_T[(size_t)4096 * 4096];     // mixed     [slab][kr][o]   (64 MB)
__device__ float g_Z[(size_t)1048576 * 64];    // xx+xy     [b][m][n][o]    (256 MB)

// ----------------------------- basis ---------------------------------------
__global__ void k_basis() {
    int idx = blockIdx.x * 256 + threadIdx.x;   // 16384 entries
    if (idx >= 16384) return;
    int n = idx >> 6, kr = idx & 63;
    int k = kr >> 1;
    double th = 2.0 * PI_D * (double)k * (double)n / 256.0;
    double c = cos(th), s = sin(th);
    // rfft ortho: X[k] = (1/16) sum_n x[n] (cos - i sin)
    g_Ft[idx] = (float)(((kr & 1) ? -s : c) * 0.0625);
    // irfft ortho of 32-mode padded spectrum:
    // y[n] = (1/16)[Re Y0 + sum_{k=1}^{31} 2(Re Yk cos - Im Yk sin)]
    double v;
    if (k == 0) v = (kr & 1) ? 0.0 : 0.0625;
    else        v = ((kr & 1) ? -2.0 * s : 2.0 * c) * 0.0625;
    g_Cit[idx] = (float)v;
}

// --------------------- weight transpose [c][o][k] -> [k][c][o] --------------
__global__ void k_wt(const float* __restrict__ w1re, const float* __restrict__ w1im,
                     const float* __restrict__ w2re, const float* __restrict__ w2im) {
    int idx = blockIdx.x * 256 + threadIdx.x;
    if (idx >= 131072) return;
    int k = idx >> 12, c = (idx >> 6) & 63, o = idx & 63;
    int src = (c * 64 + o) * 32 + k;
    g_w1t[idx]          = w1re[src];
    g_w1t[131072 + idx] = w1im[src];
    g_w2t[idx]          = w2re[src];
    g_w2t[131072 + idx] = w2im[src];
}

// --------------------- forward DFT GEMM per slab ----------------------------
// S[slab][kr][c] = sum_n Ft[n][kr] * x[slab][n][c]. 256 threads, 4x4 tiles.
__global__ __launch_bounds__(256) void k_fwd(const float* __restrict__ x, int xpath) {
    extern __shared__ float sm[];
    float* xs = sm;          // [256][64]
    float* fs = sm + 16384;  // [256][64]
    int t = threadIdx.x;
    int slab = blockIdx.x;

    if (xpath) {
        // slab = (b, n); rows are m with stride 16384 floats
        size_t base = (size_t)(slab >> 8) * 4194304u + (size_t)(slab & 255) * 64u;
        for (int i = t; i < 4096; i += 256) {
            int m = i >> 4, c4 = (i & 15) * 4;
            ((float4*)xs)[i] = *(const float4*)(x + base + (size_t)m * 16384u + c4);
        }
    } else {
        const float4* src = (const float4*)(x + (size_t)slab * 16384u);
        for (int i = t; i < 4096; i += 256) ((float4*)xs)[i] = src[i];
    }
    {
        const float4* fsrc = (const float4*)g_Ft;
        for (int i = t; i < 4096; i += 256) ((float4*)fs)[i] = fsrc[i];
    }
    __syncthreads();

    int tx = t & 15, ty = t >> 4;
    float acc[4][4] = {};
    const float* xp = xs + tx * 4;
    const float* fp = fs + ty * 4;
#pragma unroll 8
    for (int n = 0; n < 256; n++) {
        float4 xv = *(const float4*)(xp + n * 64);
        float4 fv = *(const float4*)(fp + n * 64);
        float xvv[4] = {xv.x, xv.y, xv.z, xv.w};
        float fvv[4] = {fv.x, fv.y, fv.z, fv.w};
#pragma unroll
        for (int i = 0; i < 4; i++)
#pragma unroll
            for (int j = 0; j < 4; j++) acc[i][j] = fmaf(fvv[i], xvv[j], acc[i][j]);
    }
    float* Sp = g_S + (size_t)slab * 4096u + (size_t)(ty * 4) * 64u + tx * 4;
#pragma unroll
    for (int i = 0; i < 4; i++) {
        float4 v = make_float4(acc[i][0], acc[i][1], acc[i][2], acc[i][3]);
        *(float4*)(Sp + i * 64) = v;
    }
}

// --------------------- per-mode complex channel mix -------------------------
// grid = (64 slab-tiles, 32 k). T[slab][2k][o]=Re, [2k+1][o]=Im.
__global__ __launch_bounds__(256) void k_mix(int which) {
    extern __shared__ float sm[];
    float* Ss  = sm;             // [64 slabs][132]  (re row 0..63, im row 64..127)
    float* Wre = sm + 64 * 132;  // [64c][64o]
    float* Wim = Wre + 4096;
    const float* wt = which ? g_w2t : g_w1t;
    int t = threadIdx.x;
    int k = blockIdx.y;
    int s0 = blockIdx.x * 64;

    for (int i = t; i < 2048; i += 256) {
        int s = i >> 5, q = (i & 31) * 4;
        float4 v = *(const float4*)(g_S + (size_t)(s0 + s) * 4096u + (size_t)k * 128u + q);
        *(float4*)(Ss + s * 132 + q) = v;
    }
    for (int i = t; i < 1024; i += 256) {
        ((float4*)Wre)[i] = *(const float4*)(wt + (size_t)k * 4096u + i * 4);
        ((float4*)Wim)[i] = *(const float4*)(wt + 131072u + (size_t)k * 4096u + i * 4);
    }
    __syncthreads();

    int tx = t & 15, ty = t >> 4;
    float ar[4][4] = {}, ai[4][4] = {};
#pragma unroll 4
    for (int c = 0; c < 64; c++) {
        float sr[4], si[4];
#pragma unroll
        for (int i = 0; i < 4; i++) {
            sr[i] = Ss[(ty * 4 + i) * 132 + c];
            si[i] = Ss[(ty * 4 + i) * 132 + 64 + c];
        }
        float4 wr = *(const float4*)(Wre + c * 64 + tx * 4);
        float4 wi = *(const float4*)(Wim + c * 64 + tx * 4);
        float wrr[4] = {wr.x, wr.y, wr.z, wr.w};
        float wii[4] = {wi.x, wi.y, wi.z, wi.w};
#pragma unroll
        for (int i = 0; i < 4; i++)
#pragma unroll
            for (int j = 0; j < 4; j++) {
                ar[i][j] = fmaf(sr[i], wrr[j], ar[i][j]);
                ar[i][j] = fmaf(-si[i], wii[j], ar[i][j]);
                ai[i][j] = fmaf(sr[i], wii[j], ai[i][j]);
                ai[i][j] = fmaf(si[i], wrr[j], ai[i][j]);
            }
    }
#pragma unroll
    for (int i = 0; i < 4; i++) {
        float* Tp = g_T + (size_t)(s0 + ty * 4 + i) * 4096u + (size_t)(2 * k) * 64u + tx * 4;
        *(float4*)Tp        = make_float4(ar[i][0], ar[i][1], ar[i][2], ar[i][3]);
        *(float4*)(Tp + 64) = make_float4(ai[i][0], ai[i][1], ai[i][2], ai[i][3]);
    }
}

// --------------------- inverse DFT GEMM per slab ----------------------------
// y[n][o] = sum_kr Cit[n][kr] * T[slab][kr][o]. 8x8 tiles per thread.
__global__ __launch_bounds__(256) void k_inv(int xpath) {
    extern __shared__ float sm[];
    float* Cs = sm;           // [256][65]
    float* Ts = sm + 16640;   // [64][64]
    int t = threadIdx.x;
    int slab = blockIdx.x;

    for (int i = t; i < 16384; i += 256)
        Cs[(i >> 6) * 65 + (i & 63)] = g_Cit[i];
    {
        const float4* tsrc = (const float4*)(g_T + (size_t)slab * 4096u);
        for (int i = t; i < 1024; i += 256) ((float4*)Ts)[i] = tsrc[i];
    }
    __syncthreads();

    int tx = t & 7, ty = t >> 3;
    int n0 = ty * 8;
    float acc[8][8] = {};
#pragma unroll 2
    for (int kr = 0; kr < 64; kr++) {
        float4 t0 = *(const float4*)(Ts + kr * 64 + tx * 4);
        float4 t1 = *(const float4*)(Ts + kr * 64 + 32 + tx * 4);
        float tv[8] = {t0.x, t0.y, t0.z, t0.w, t1.x, t1.y, t1.z, t1.w};
#pragma unroll
        for (int i = 0; i < 8; i++) {
            float cv = Cs[(n0 + i) * 65 + kr];
#pragma unroll
            for (int j = 0; j < 8; j++) acc[i][j] = fmaf(cv, tv[j], acc[i][j]);
        }
    }
    if (!xpath) {
        float* dst = g_Z + (size_t)slab * 16384u;
#pragma unroll
        for (int i = 0; i < 8; i++) {
            float* p = dst + (size_t)(n0 + i) * 64u + tx * 4;
            *(float4*)p        = make_float4(acc[i][0], acc[i][1], acc[i][2], acc[i][3]);
            *(float4*)(p + 32) = make_float4(acc[i][4], acc[i][5], acc[i][6], acc[i][7]);
        }
    } else {
        // slab = (b, ncol); position index is m -> stride 16384 in Z; accumulate.
        size_t base = (size_t)(slab >> 8) * 4194304u + (size_t)(slab & 255) * 64u;
#pragma unroll
        for (int i = 0; i < 8; i++) {
            float* p = g_Z + base + (size_t)(n0 + i) * 16384u + tx * 4;
            float4 v0 = *(float4*)p, v1 = *(float4*)(p + 32);
            v0.x += acc[i][0]; v0.y += acc[i][1]; v0.z += acc[i][2]; v0.w += acc[i][3];
            v1.x += acc[i][4]; v1.y += acc[i][5]; v1.z += acc[i][6]; v1.w += acc[i][7];
            *(float4*)p = v0; *(float4*)(p + 32) = v1;
        }
    }
}

// --------------------- fused FeedForward + LayerNorm ------------------------
// 32 rows/block, 256 threads. h=relu(zW1+b1); y=hW2+b2; LN(y)*g+b.
__global__ __launch_bounds__(256) void k_ff(
    const float* __restrict__ w1, const float* __restrict__ b1,
    const float* __restrict__ w2, const float* __restrict__ b2,
    const float* __restrict__ lg, const float* __restrict__ lb,
    float* __restrict__ out)
{
    extern __shared__ float sm[];
    float* W1s = sm;              // [64][256]
    float* W2s = W1s + 16384;     // [256][64]
    float* zs  = W2s + 16384;     // [32][65]  (later reused for y)
    float* hs  = zs + 2080;       // [32][260]
    float* b1s = hs + 8320;       // 256
    float* b2s = b1s + 256;       // 64
    float* gs  = b2s + 64;        // 64
    float* bs  = gs + 64;         // 64
    float* mus = bs + 64;         // 32
    float* rss = mus + 32;        // 32
    int t = threadIdx.x;

    for (int i = t; i < 4096; i += 256) {
        ((float4*)W1s)[i] = ((const float4*)w1)[i];
        ((float4*)W2s)[i] = ((const float4*)w2)[i];
    }
    b1s[t] = b1[t];
    if (t < 64) { b2s[t] = b2[t]; gs[t] = lg[t]; bs[t] = lb[t]; }

    size_t r0 = (size_t)blockIdx.x * 32u;
    for (int i = t; i < 2048; i += 256)
        zs[(i >> 6) * 65 + (i & 63)] = g_Z[r0 * 64u + (size_t)i];
    __syncthreads();

    int tx = t & 7, row = t >> 3;

    // stage 1: h[row][j], each thread 8 chunks of 4 j's (j = i*32 + tx*4 + q)
    float acc[8][4];
#pragma unroll
    for (int i = 0; i < 8; i++) {
        float4 bv = *(const float4*)(b1s + i * 32 + tx * 4);
        acc[i][0] = bv.x; acc[i][1] = bv.y; acc[i][2] = bv.z; acc[i][3] = bv.w;
    }
#pragma unroll 4
    for (int c = 0; c < 64; c++) {
        float zb = zs[row * 65 + c];
#pragma unroll
        for (int i = 0; i < 8; i++) {
            float4 w = *(const float4*)(W1s + c * 256 + i * 32 + tx * 4);
            acc[i][0] = fmaf(zb, w.x, acc[i][0]);
            acc[i][1] = fmaf(zb, w.y, acc[i][1]);
            acc[i][2] = fmaf(zb, w.z, acc[i][2]);
            acc[i][3] = fmaf(zb, w.w, acc[i][3]);
        }
    }
#pragma unroll
    for (int i = 0; i < 8; i++) {
        float4 h = make_float4(fmaxf(acc[i][0], 0.f), fmaxf(acc[i][1], 0.f),
                               fmaxf(acc[i][2], 0.f), fmaxf(acc[i][3], 0.f));
        *(float4*)(hs + row * 260 + i * 32 + tx * 4) = h;
    }
    __syncthreads();

    // stage 2: y[row][o], o in {tx*4..+3} U {32+tx*4..+3}
    float a0[4], a1[4];
    {
        float4 v0 = *(const float4*)(b2s + tx * 4);
        float4 v1 = *(const float4*)(b2s + 32 + tx * 4);
        a0[0]=v0.x; a0[1]=v0.y; a0[2]=v0.z; a0[3]=v0.w;
        a1[0]=v1.x; a1[1]=v1.y; a1[2]=v1.z; a1[3]=v1.w;
    }
#pragma unroll 8
    for (int j = 0; j < 256; j++) {
        float hb = hs[row * 260 + j];
        float4 w0 = *(const float4*)(W2s + j * 64 + tx * 4);
        float4 w1v = *(const float4*)(W2s + j * 64 + 32 + tx * 4);
        a0[0] = fmaf(hb, w0.x, a0[0]); a0[1] = fmaf(hb, w0.y, a0[1]);
        a0[2] = fmaf(hb, w0.z, a0[2]); a0[3] = fmaf(hb, w0.w, a0[3]);
        a1[0] = fmaf(hb, w1v.x, a1[0]); a1[1] = fmaf(hb, w1v.y, a1[1]);
        a1[2] = fmaf(hb, w1v.z, a1[2]); a1[3] = fmaf(hb, w1v.w, a1[3]);
    }
    __syncthreads();                 // zs free to reuse as y
    {
        float* yp = zs + row * 65;
        yp[tx*4+0] = a0[0]; yp[tx*4+1] = a0[1]; yp[tx*4+2] = a0[2]; yp[tx*4+3] = a0[3];
        yp[32+tx*4+0] = a1[0]; yp[32+tx*4+1] = a1[1]; yp[32+tx*4+2] = a1[2]; yp[32+tx*4+3] = a1[3];
    }
    __syncthreads();

    if (t < 32) {
        const float* y = zs + t * 65;
        float s = 0.f, s2 = 0.f;
#pragma unroll 8
        for (int c = 0; c < 64; c++) { float v = y[c]; s += v; s2 += v * v; }
        float mu = s * 0.015625f;
        float var = s2 * 0.015625f - mu * mu;
        mus[t] = mu; rss[t] = rsqrtf(var + 1e-5f);
    }
    __syncthreads();

    {
        float mu = mus[row], rs = rss[row];
        const float* y = zs + row * 65;
        int ob = tx * 8;
        float4 o0, o1;
        o0.x = (y[ob+0]-mu)*rs*gs[ob+0] + bs[ob+0];
        o0.y = (y[ob+1]-mu)*rs*gs[ob+1] + bs[ob+1];
        o0.z = (y[ob+2]-mu)*rs*gs[ob+2] + bs[ob+2];
        o0.w = (y[ob+3]-mu)*rs*gs[ob+3] + bs[ob+3];
        o1.x = (y[ob+4]-mu)*rs*gs[ob+4] + bs[ob+4];
        o1.y = (y[ob+5]-mu)*rs*gs[ob+5] + bs[ob+5];
        o1.z = (y[ob+6]-mu)*rs*gs[ob+6] + bs[ob+6];
        o1.w = (y[ob+7]-mu)*rs*gs[ob+7] + bs[ob+7];
        float* op = out + (r0 + (size_t)row) * 64u + ob;
        *(float4*)op = o0;
        *(float4*)(op + 4) = o1;
    }
}

// ----------------------------- launch ---------------------------------------
extern "C" void kernel_launch(void* const* d_in, const int* in_sizes, int n_in,
                              void* d_out, int out_size) {
    (void)in_sizes; (void)n_in; (void)out_size;
    const float* x    = (const float*)d_in[0];
    const float* w1re = (const float*)d_in[1];
    const float* w1im = (const float*)d_in[2];
    const float* w2re = (const float*)d_in[3];
    const float* w2im = (const float*)d_in[4];
    const float* ffw1 = (const float*)d_in[5];
    const float* ffb1 = (const float*)d_in[6];
    const float* ffw2 = (const float*)d_in[7];
    const float* ffb2 = (const float*)d_in[8];
    const float* lng  = (const float*)d_in[9];
    const float* lnb  = (const float*)d_in[10];
    float* out = (float*)d_out;

    cudaFuncSetAttribute(k_fwd, cudaFuncAttributeMaxDynamicSharedMemorySize, 131072);
    cudaFuncSetAttribute(k_mix, cudaFuncAttributeMaxDynamicSharedMemorySize, 66560);
    cudaFuncSetAttribute(k_inv, cudaFuncAttributeMaxDynamicSharedMemorySize, 82944);
    cudaFuncSetAttribute(k_ff,  cudaFuncAttributeMaxDynamicSharedMemorySize, 174720);

    k_basis<<<64, 256>>>();
    k_wt<<<512, 256>>>(w1re, w1im, w2re, w2im);

    // y-path: slabs = (b, m), transform along n
    k_fwd<<<4096, 256, 131072>>>(x, 0);
    k_mix<<<dim3(64, 32), 256, 66560>>>(0);
    k_inv<<<4096, 256, 82944>>>(0);

    // x-path: slabs = (b, n), transform along m, accumulate into Z
    k_fwd<<<4096, 256, 131072>>>(x, 1);
    k_mix<<<dim3(64, 32), 256, 66560>>>(1);
    k_inv<<<4096, 256, 82944>>>(1);

    k_ff<<<32768, 256, 174720>>>(ffw1, ffb1, ffw2, ffb2, lng, lnb, out);
}

// round 4
// speedup vs baseline: 2.2818x; 2.2818x over previous
#include <cuda_runtime.h>
#include <math.h>

// B=16, M=N=256, C=OUT=64, modes=32/axis, FF_HID=256.
// Slabs: 4096 = B*M (y-path) or B*N (x-path). Each slab: 256 pos x 64 ch.

#define PI_D 3.14159265358979323846
typedef unsigned long long u64;

// ---------------- packed f32x2 helpers (sm_103a FFMA2) ----------------------
__device__ __forceinline__ u64 pack2(float lo, float hi) {
    u64 r; asm("mov.b64 %0,{%1,%2};" : "=l"(r) : "f"(lo), "f"(hi)); return r;
}
__device__ __forceinline__ float2 unpk(u64 v) {
    float2 f; asm("mov.b64 {%0,%1},%2;" : "=f"(f.x), "=f"(f.y) : "l"(v)); return f;
}
__device__ __forceinline__ void fma2(u64& d, u64 a, u64 b) {
    asm("fma.rn.f32x2 %0,%1,%2,%0;" : "+l"(d) : "l"(a), "l"(b));
}

// ----------------------------- device scratch ------------------------------
__device__ float g_Ft [256 * 64];            // forward DFT [n][kr]
__device__ float g_Cit[256 * 64];            // inverse DFT [n][kr]
__device__ float g_w1t[2 * 32 * 64 * 64];    // [re|im][k][c][o]
__device__ float g_w2t[2 * 32 * 64 * 64];
__device__ float g_S[(size_t)4096 * 4096];   // spectra [slab][kr][c]
__device__ float g_T[(size_t)4096 * 4096];   // mixed   [slab][kr][o]
__device__ float g_Z[(size_t)1048576 * 64];  // xx+xy   [b][m][n][o]

// ----------------------------- basis ---------------------------------------
__global__ void k_basis() {
    int idx = blockIdx.x * 256 + threadIdx.x;
    if (idx >= 16384) return;
    int n = idx >> 6, kr = idx & 63;
    int k = kr >> 1;
    double th = 2.0 * PI_D * (double)k * (double)n / 256.0;
    double c = cos(th), s = sin(th);
    g_Ft[idx] = (float)(((kr & 1) ? -s : c) * 0.0625);
    double v;
    if (k == 0) v = (kr & 1) ? 0.0 : 0.0625;
    else        v = ((kr & 1) ? -2.0 * s : 2.0 * c) * 0.0625;
    g_Cit[idx] = (float)v;
}

// --------------------- weight transpose [c][o][k] -> [k][c][o] --------------
__global__ void k_wt(const float* __restrict__ w1re, const float* __restrict__ w1im,
                     const float* __restrict__ w2re, const float* __restrict__ w2im) {
    int idx = blockIdx.x * 256 + threadIdx.x;
    if (idx >= 131072) return;
    int k = idx >> 12, c = (idx >> 6) & 63, o = idx & 63;
    int src = (c * 64 + o) * 32 + k;
    g_w1t[idx]          = w1re[src];
    g_w1t[131072 + idx] = w1im[src];
    g_w2t[idx]          = w2re[src];
    g_w2t[131072 + idx] = w2im[src];
}

// --------------------- forward DFT GEMM -------------------------------------
// 2 slabs/block, 128 thr/slab, 8kr x 4c tiles, n split in 2 halves.
// S[slab][kr][c] = sum_n Ft[n][kr] * x[slab][n][c].
__global__ __launch_bounds__(256) void k_fwd(const float* __restrict__ x, int xpath) {
    extern __shared__ float sm[];
    float* fs = sm;           // [128][64]
    float* xs = sm + 8192;    // [2][128][64]
    int t = threadIdx.x;
    int sl = t >> 7, s = t & 127;
    int tx = s & 15, ty = s >> 4;   // c-group 16x4, kr-group 8x8
    int slab0 = blockIdx.x * 2;

    u64 acc[4][4] = {};  // [kr-pair][c]; 0ull == (0.f,0.f)

    for (int h = 0; h < 2; h++) {
        for (int i = t; i < 2048; i += 256)
            ((float4*)fs)[i] = ((const float4*)g_Ft)[h * 2048 + i];
        if (!xpath) {
            for (int i = t; i < 4096; i += 256) {
                int ssl = i >> 11, j = i & 2047;
                ((float4*)xs)[i] =
                    *((const float4*)(x + (size_t)(slab0 + ssl) * 16384u + (size_t)h * 8192u) + j);
            }
        } else {
            for (int i = t; i < 4096; i += 256) {
                int ssl = i >> 11, j = i & 2047;
                int mm = j >> 4, c4 = (j & 15) * 4;
                int slab = slab0 + ssl;
                size_t base = (size_t)(slab >> 8) * 4194304u + (size_t)(slab & 255) * 64u;
                ((float4*)xs)[i] = *(const float4*)(x + base + (size_t)(h * 128 + mm) * 16384u + c4);
            }
        }
        __syncthreads();

        const float* fb = fs + ty * 8;
        const float* xb = xs + sl * 8192 + tx * 4;
#pragma unroll 4
        for (int n = 0; n < 128; n++) {
            u64 f0 = *(const u64*)(fb + n * 64 + 0);
            u64 f1 = *(const u64*)(fb + n * 64 + 2);
            u64 f2 = *(const u64*)(fb + n * 64 + 4);
            u64 f3 = *(const u64*)(fb + n * 64 + 6);
            float4 xv = *(const float4*)(xb + n * 64);
            u64 x0 = pack2(xv.x, xv.x), x1 = pack2(xv.y, xv.y);
            u64 x2 = pack2(xv.z, xv.z), x3 = pack2(xv.w, xv.w);
            fma2(acc[0][0], f0, x0); fma2(acc[0][1], f0, x1);
            fma2(acc[0][2], f0, x2); fma2(acc[0][3], f0, x3);
            fma2(acc[1][0], f1, x0); fma2(acc[1][1], f1, x1);
            fma2(acc[1][2], f1, x2); fma2(acc[1][3], f1, x3);
            fma2(acc[2][0], f2, x0); fma2(acc[2][1], f2, x1);
            fma2(acc[2][2], f2, x2); fma2(acc[2][3], f2, x3);
            fma2(acc[3][0], f3, x0); fma2(acc[3][1], f3, x1);
            fma2(acc[3][2], f3, x2); fma2(acc[3][3], f3, x3);
        }
        __syncthreads();
    }

    float* Sp = g_S + (size_t)(slab0 + sl) * 4096u + (size_t)(ty * 8) * 64u + tx * 4;
#pragma unroll
    for (int p = 0; p < 4; p++) {
        float2 a0 = unpk(acc[p][0]), a1 = unpk(acc[p][1]);
        float2 a2 = unpk(acc[p][2]), a3 = unpk(acc[p][3]);
        *(float4*)(Sp + (2 * p) * 64)     = make_float4(a0.x, a1.x, a2.x, a3.x);
        *(float4*)(Sp + (2 * p + 1) * 64) = make_float4(a0.y, a1.y, a2.y, a3.y);
    }
}

// --------------------- per-mode complex channel mix -------------------------
__global__ __launch_bounds__(256) void k_mix(int which) {
    extern __shared__ float sm[];
    float* Ss  = sm;             // [64 slabs][132] (re 0..63, im 64..127)
    float* Wre = sm + 64 * 132;  // [64c][64o]
    float* Wim = Wre + 4096;
    const float* wt = which ? g_w2t : g_w1t;
    int t = threadIdx.x;
    int k = blockIdx.y;
    int s0 = blockIdx.x * 64;

    for (int i = t; i < 2048; i += 256) {
        int s = i >> 5, q = (i & 31) * 4;
        float4 v = *(const float4*)(g_S + (size_t)(s0 + s) * 4096u + (size_t)k * 128u + q);
        *(float4*)(Ss + s * 132 + q) = v;
    }
    for (int i = t; i < 1024; i += 256) {
        ((float4*)Wre)[i] = *(const float4*)(wt + (size_t)k * 4096u + i * 4);
        ((float4*)Wim)[i] = *(const float4*)(wt + 131072u + (size_t)k * 4096u + i * 4);
    }
    __syncthreads();

    int tx = t & 15, ty = t >> 4;
    u64 ar[4][2] = {}, ai[4][2] = {};
#pragma unroll 4
    for (int c = 0; c < 64; c++) {
        ulonglong2 wr = *(const ulonglong2*)(Wre + c * 64 + tx * 4);
        ulonglong2 wi = *(const ulonglong2*)(Wim + c * 64 + tx * 4);
#pragma unroll
        for (int i = 0; i < 4; i++) {
            float srv = Ss[(ty * 4 + i) * 132 + c];
            float siv = Ss[(ty * 4 + i) * 132 + 64 + c];
            u64 sr2 = pack2(srv, srv);
            u64 si2 = pack2(siv, siv);
            u64 ns2 = pack2(-siv, -siv);
            fma2(ar[i][0], sr2, wr.x); fma2(ar[i][0], ns2, wi.x);
            fma2(ar[i][1], sr2, wr.y); fma2(ar[i][1], ns2, wi.y);
            fma2(ai[i][0], sr2, wi.x); fma2(ai[i][0], si2, wr.x);
            fma2(ai[i][1], sr2, wi.y); fma2(ai[i][1], si2, wr.y);
        }
    }
#pragma unroll
    for (int i = 0; i < 4; i++) {
        float* Tp = g_T + (size_t)(s0 + ty * 4 + i) * 4096u + (size_t)(2 * k) * 64u + tx * 4;
        float2 r0 = unpk(ar[i][0]), r1 = unpk(ar[i][1]);
        float2 m0 = unpk(ai[i][0]), m1 = unpk(ai[i][1]);
        *(float4*)Tp        = make_float4(r0.x, r0.y, r1.x, r1.y);
        *(float4*)(Tp + 64) = make_float4(m0.x, m0.y, m1.x, m1.y);
    }
}

// --------------------- inverse DFT GEMM -------------------------------------
// y[n][o] = sum_kr Cit[n][kr] * T[slab][kr][o]. 8n x 8o tiles.
__global__ __launch_bounds__(256) void k_inv(int xpath) {
    extern __shared__ float sm[];
    float* Cs = sm;           // [256][65]
    float* Ts = sm + 16640;   // [64][64]
    int t = threadIdx.x;
    int slab = blockIdx.x;

    for (int i = t; i < 16384; i += 256)
        Cs[(i >> 6) * 65 + (i & 63)] = g_Cit[i];
    {
        const float4* tsrc = (const float4*)(g_T + (size_t)slab * 4096u);
        for (int i = t; i < 1024; i += 256) ((float4*)Ts)[i] = tsrc[i];
    }
    __syncthreads();

    int tx = t & 7, ty = t >> 3;
    int n0 = ty * 8;
    u64 acc[8][4] = {};
#pragma unroll 2
    for (int kr = 0; kr < 64; kr++) {
        ulonglong2 t0 = *(const ulonglong2*)(Ts + kr * 64 + tx * 4);
        ulonglong2 t1 = *(const ulonglong2*)(Ts + kr * 64 + 32 + tx * 4);
#pragma unroll
        for (int i = 0; i < 8; i++) {
            float cv = Cs[(n0 + i) * 65 + kr];
            u64 c2 = pack2(cv, cv);
            fma2(acc[i][0], c2, t0.x); fma2(acc[i][1], c2, t0.y);
            fma2(acc[i][2], c2, t1.x); fma2(acc[i][3], c2, t1.y);
        }
    }
    if (!xpath) {
        float* dst = g_Z + (size_t)slab * 16384u;
#pragma unroll
        for (int i = 0; i < 8; i++) {
            float* p = dst + (size_t)(n0 + i) * 64u + tx * 4;
            float2 a0 = unpk(acc[i][0]), a1 = unpk(acc[i][1]);
            float2 a2 = unpk(acc[i][2]), a3 = unpk(acc[i][3]);
            *(float4*)p        = make_float4(a0.x, a0.y, a1.x, a1.y);
            *(float4*)(p + 32) = make_float4(a2.x, a2.y, a3.x, a3.y);
        }
    } else {
        size_t base = (size_t)(slab >> 8) * 4194304u + (size_t)(slab & 255) * 64u;
#pragma unroll
        for (int i = 0; i < 8; i++) {
            float* p = g_Z + base + (size_t)(n0 + i) * 16384u + tx * 4;
            float4 v0 = *(float4*)p, v1 = *(float4*)(p + 32);
            float2 a0 = unpk(acc[i][0]), a1 = unpk(acc[i][1]);
            float2 a2 = unpk(acc[i][2]), a3 = unpk(acc[i][3]);
            v0.x += a0.x; v0.y += a0.y; v0.z += a1.x; v0.w += a1.y;
            v1.x += a2.x; v1.y += a2.y; v1.z += a3.x; v1.w += a3.y;
            *(float4*)p = v0; *(float4*)(p + 32) = v1;
        }
    }
}

// --------------------- fused FeedForward + LayerNorm ------------------------
// 64 rows/block, 256 threads.
__global__ __launch_bounds__(256) void k_ff(
    const float* __restrict__ w1, const float* __restrict__ b1,
    const float* __restrict__ w2, const float* __restrict__ b2,
    const float* __restrict__ lg, const float* __restrict__ lb,
    float* __restrict__ out)
{
    extern __shared__ float sm[];
    float* W1s = sm;                 // [64][256]           16384
    float* W2s = W1s + 16384;        // [256][64]           16384
    float* Zs  = W2s + 16384;        // [64][68] (later y)   4352
    float* Hs  = Zs + 4352;          // [64][260]           16640
    float* b1s = Hs + 16640;         // 256
    float* b2s = b1s + 256;          // 64
    float* gs  = b2s + 64;           // 64
    float* bs  = gs + 64;            // 64
    float* mus = bs + 64;            // 64
    float* rss = mus + 64;           // 64
    float* Pp  = W1s;                // partials overlay: 3*64*68 = 13056
    int t = threadIdx.x;

    for (int i = t; i < 4096; i += 256) {
        ((float4*)W1s)[i] = ((const float4*)w1)[i];
        ((float4*)W2s)[i] = ((const float4*)w2)[i];
    }
    b1s[t] = b1[t];
    if (t < 64) { b2s[t] = b2[t]; gs[t] = lg[t]; bs[t] = lb[t]; }

    size_t r0 = (size_t)blockIdx.x * 64u;
    {
        const float4* zsrc = (const float4*)(g_Z + r0 * 64u);
        for (int i = t; i < 1024; i += 256) {
            int row = i >> 4, c4 = (i & 15) * 4;
            *(float4*)(Zs + row * 68 + c4) = zsrc[i];
        }
    }
    __syncthreads();

    // ---- stage 1: H = relu(Z @ W1 + b1), 8 rows x 8 cols per thread -------
    {
        int txs = t & 31, tys = t >> 5;
        u64 acc[8][4];
        {
            ulonglong2 bA = *(const ulonglong2*)(b1s + txs * 4);
            ulonglong2 bB = *(const ulonglong2*)(b1s + 128 + txs * 4);
#pragma unroll
            for (int i = 0; i < 8; i++) {
                acc[i][0] = bA.x; acc[i][1] = bA.y;
                acc[i][2] = bB.x; acc[i][3] = bB.y;
            }
        }
        const float* zb = Zs + tys * 8 * 68;
#pragma unroll 4
        for (int c = 0; c < 64; c++) {
            ulonglong2 wA = *(const ulonglong2*)(W1s + c * 256 + txs * 4);
            ulonglong2 wB = *(const ulonglong2*)(W1s + c * 256 + 128 + txs * 4);
#pragma unroll
            for (int i = 0; i < 8; i++) {
                float z = zb[i * 68 + c];
                u64 z2 = pack2(z, z);
                fma2(acc[i][0], z2, wA.x); fma2(acc[i][1], z2, wA.y);
                fma2(acc[i][2], z2, wB.x); fma2(acc[i][3], z2, wB.y);
            }
        }
#pragma unroll
        for (int i = 0; i < 8; i++) {
            float* hp = Hs + (tys * 8 + i) * 260;
            float2 a0 = unpk(acc[i][0]), a1 = unpk(acc[i][1]);
            float2 a2 = unpk(acc[i][2]), a3 = unpk(acc[i][3]);
            *(float4*)(hp + txs * 4) = make_float4(
                fmaxf(a0.x, 0.f), fmaxf(a0.y, 0.f), fmaxf(a1.x, 0.f), fmaxf(a1.y, 0.f));
            *(float4*)(hp + 128 + txs * 4) = make_float4(
                fmaxf(a2.x, 0.f), fmaxf(a2.y, 0.f), fmaxf(a3.x, 0.f), fmaxf(a3.y, 0.f));
        }
    }
    __syncthreads();

    // ---- stage 2: Y = H @ W2 + b2, 8x8 tiles, 4-way k-split + reduce ------
    int rg = t & 7, og = (t >> 3) & 7, q = t >> 6;
    u64 acc[8][4] = {};
    {
        int j0 = q * 64;
#pragma unroll 4
        for (int jj = 0; jj < 64; jj++) {
            int j = j0 + jj;
            ulonglong2 wA = *(const ulonglong2*)(W2s + j * 64 + og * 4);
            ulonglong2 wB = *(const ulonglong2*)(W2s + j * 64 + 32 + og * 4);
#pragma unroll
            for (int i = 0; i < 8; i++) {
                float h = Hs[(rg + 8 * i) * 260 + j];
                u64 h2 = pack2(h, h);
                fma2(acc[i][0], h2, wA.x); fma2(acc[i][1], h2, wA.y);
                fma2(acc[i][2], h2, wB.x); fma2(acc[i][3], h2, wB.y);
            }
        }
        if (q) {
            float* P = Pp + (q - 1) * 4352;
#pragma unroll
            for (int i = 0; i < 8; i++) {
                int row = rg + 8 * i;
                float2 a0 = unpk(acc[i][0]), a1 = unpk(acc[i][1]);
                float2 a2 = unpk(acc[i][2]), a3 = unpk(acc[i][3]);
                *(float4*)(P + row * 68 + og * 4)      = make_float4(a0.x, a0.y, a1.x, a1.y);
                *(float4*)(P + row * 68 + 32 + og * 4) = make_float4(a2.x, a2.y, a3.x, a3.y);
            }
        }
    }
    __syncthreads();

    if (q == 0) {
        float4 bv0 = *(const float4*)(b2s + og * 4);
        float4 bv1 = *(const float4*)(b2s + 32 + og * 4);
#pragma unroll
        for (int i = 0; i < 8; i++) {
            int row = rg + 8 * i;
            float2 a0 = unpk(acc[i][0]), a1 = unpk(acc[i][1]);
            float2 a2 = unpk(acc[i][2]), a3 = unpk(acc[i][3]);
            float4 v0 = make_float4(a0.x + bv0.x, a0.y + bv0.y, a1.x + bv0.z, a1.y + bv0.w);
            float4 v1 = make_float4(a2.x + bv1.x, a2.y + bv1.y, a3.x + bv1.z, a3.y + bv1.w);
#pragma unroll
            for (int s = 0; s < 3; s++) {
                float4 p0 = *(const float4*)(Pp + s * 4352 + row * 68 + og * 4);
                float4 p1 = *(const float4*)(Pp + s * 4352 + row * 68 + 32 + og * 4);
                v0.x += p0.x; v0.y += p0.y; v0.z += p0.z; v0.w += p0.w;
                v1.x += p1.x; v1.y += p1.y; v1.z += p1.z; v1.w += p1.w;
            }
            *(float4*)(Zs + row * 68 + og * 4)      = v0;
            *(float4*)(Zs + row * 68 + 32 + og * 4) = v1;
        }
    }
    __syncthreads();

    if (t < 64) {
        const float* y = Zs + t * 68;
        float s = 0.f, s2 = 0.f;
#pragma unroll 8
        for (int c = 0; c < 64; c++) { float v = y[c]; s += v; s2 += v * v; }
        float mu = s * 0.015625f;
        float var = s2 * 0.015625f - mu * mu;
        mus[t] = mu; rss[t] = rsqrtf(var + 1e-5f);
    }
    __syncthreads();

    {
        int row = t >> 2, cg = (t & 3) * 16;
        float mu = mus[row], rs = rss[row];
        const float* y = Zs + row * 68;
        float* op = out + (r0 + (size_t)row) * 64u;
#pragma unroll
        for (int kk = 0; kk < 4; kk++) {
            int c = cg + kk * 4;
            float4 v = *(const float4*)(y + c);
            float4 o;
            o.x = (v.x - mu) * rs * gs[c + 0] + bs[c + 0];
            o.y = (v.y - mu) * rs * gs[c + 1] + bs[c + 1];
            o.z = (v.z - mu) * rs * gs[c + 2] + bs[c + 2];
            o.w = (v.w - mu) * rs * gs[c + 3] + bs[c + 3];
            *(float4*)(op + c) = o;
        }
    }
}

// ----------------------------- launch ---------------------------------------
extern "C" void kernel_launch(void* const* d_in, const int* in_sizes, int n_in,
                              void* d_out, int out_size) {
    (void)in_sizes; (void)n_in; (void)out_size;
    const float* x    = (const float*)d_in[0];
    const float* w1re = (const float*)d_in[1];
    const float* w1im = (const float*)d_in[2];
    const float* w2re = (const float*)d_in[3];
    const float* w2im = (const float*)d_in[4];
    const float* ffw1 = (const float*)d_in[5];
    const float* ffb1 = (const float*)d_in[6];
    const float* ffw2 = (const float*)d_in[7];
    const float* ffb2 = (const float*)d_in[8];
    const float* lng  = (const float*)d_in[9];
    const float* lnb  = (const float*)d_in[10];
    float* out = (float*)d_out;

    cudaFuncSetAttribute(k_fwd, cudaFuncAttributeMaxDynamicSharedMemorySize, 98304);
    cudaFuncSetAttribute(k_mix, cudaFuncAttributeMaxDynamicSharedMemorySize, 66560);
    cudaFuncSetAttribute(k_inv, cudaFuncAttributeMaxDynamicSharedMemorySize, 82944);
    cudaFuncSetAttribute(k_ff,  cudaFuncAttributeMaxDynamicSharedMemorySize, 217344);

    k_basis<<<64, 256>>>();
    k_wt<<<512, 256>>>(w1re, w1im, w2re, w2im);

    // y-path
    k_fwd<<<2048, 256, 98304>>>(x, 0);
    k_mix<<<dim3(64, 32), 256, 66560>>>(0);
    k_inv<<<4096, 256, 82944>>>(0);

    // x-path (accumulates into Z)
    k_fwd<<<2048, 256, 98304>>>(x, 1);
    k_mix<<<dim3(64, 32), 256, 66560>>>(1);
    k_inv<<<4096, 256, 82944>>>(1);

    k_ff<<<16384, 256, 217344>>>(ffw1, ffb1, ffw2, ffb2, lng, lnb, out);
}